// round 5
// baseline (speedup 1.0000x reference)
#include <cuda_runtime.h>

#define N_IMG 16
#define M_PPL 30
#define K_JNT 17
#define S_RES 16
#define LS    1114112   // K*H*W = 17*256*256 floats per image

__device__ float g_partial[N_IMG][3];
__device__ unsigned int g_counter = 0;

__global__ __launch_bounds__(960)
void ae_fused(const float* __restrict__ tags,
              const int* __restrict__ joints,      // int32 (JAX x64 disabled)
              const float* __restrict__ box_scales,
              const float* __restrict__ scale_dist,
              float* __restrict__ out)
{
    const int n    = blockIdx.x;
    const int tid  = threadIdx.x;
    const int m    = tid >> 5;        // person (warp id), 0..29
    const int lane = tid & 31;
    const int h    = lane >> 4;       // K-half: 0 or 1
    const int s    = lane & 15;       // scale index

    __shared__ float s_mean[M_PPL][S_RES + 1];   // stride 17: conflict-free push reads
    __shared__ float s_pull[M_PPL];
    __shared__ float s_dscale[M_PPL];
    __shared__ float s_pushw[M_PPL];
    __shared__ int   s_valid[M_PPL];
    __shared__ unsigned s_ticket;

    // ---------------- Phase 1: one warp per person -------------------------------
    {
        const int2* jp2 = (const int2*)(joints + (n * M_PPL + m) * K_JNT * 2);
        const float* tbase = tags + (size_t)n * LS;

        // lane handles k = h, h+2, ..., <17 (h=0: 9 joints, h=1: 8)
        int2  lv[9];
        float gv[9];
        #pragma unroll
        for (int i = 0; i < 9; i++) {
            const int k = h + 2 * i;
            if (k < K_JNT) lv[i] = jp2[k];        // (loc, vis) in one 64-bit load
        }
        #pragma unroll
        for (int i = 0; i < 9; i++) {
            const int k = h + 2 * i;
            if (k < K_JNT) gv[i] = tbase[lv[i].x * S_RES + s];  // coalesced 64B/group
        }

        float sumv = 0.f; int cnt = 0;
        #pragma unroll
        for (int i = 0; i < 9; i++) {
            const int k = h + 2 * i;
            if (k < K_JNT && lv[i].y > 0) { sumv += gv[i]; cnt++; }
        }
        // combine the two K-halves (lane (1-h, s))
        sumv += __shfl_xor_sync(0xffffffffu, sumv, 16);
        cnt  += __shfl_xor_sync(0xffffffffu, cnt, 16);

        const float safe_cnt = fmaxf((float)cnt, 1.f);
        const float mean = sumv / safe_cnt;
        if (h == 0) s_mean[m][s] = mean;

        float p = 0.f;
        #pragma unroll
        for (int i = 0; i < 9; i++) {
            const int k = h + 2 * i;
            if (k < K_JNT && lv[i].y > 0) { const float d = gv[i] - mean; p += d * d; }
        }

        // scale term (each s appears twice across halves -> full-warp sums = 2x)
        const float bs  = box_scales[n * M_PPL + m];
        const float gap = fabsf(bs - scale_dist[s]);
        const float inv = 1.f / (gap + 1e-10f);
        const float am  = fabsf(mean);

        float n1 = inv * inv;
        float n2 = am * am;
        float dr = inv * am;

        // single combined reduction chain over the full warp
        #pragma unroll
        for (int off = 16; off; off >>= 1) {
            p  += __shfl_xor_sync(0xffffffffu, p,  off);
            n1 += __shfl_xor_sync(0xffffffffu, n1, off);
            n2 += __shfl_xor_sync(0xffffffffu, n2, off);
            dr += __shfl_xor_sync(0xffffffffu, dr, off);
        }

        if (lane == 0) {
            const float n1s = 0.5f * n1, n2s = 0.5f * n2, drs = 0.5f * dr;
            const float dot = drs / (fmaxf(sqrtf(n1s), 1e-12f) * fmaxf(sqrtf(n2s), 1e-12f));
            s_pull[m]   = p / (safe_cnt * (float)S_RES);
            s_dscale[m] = 1.f - dot;
            s_valid[m]  = (cnt > 0);
        }
    }
    __syncthreads();

    // ---------------- Phase 2: push — 1 pair per thread, no atomics --------------
    {
        float local = 0.f;
        if (tid < M_PPL * M_PPL) {
            const int a = tid / M_PPL;
            const int b = tid - a * M_PPL;
            if (a != b && s_valid[a] && s_valid[b]) {
                float d = 0.f;
                #pragma unroll
                for (int i = 0; i < S_RES; i++) {
                    const float t = s_mean[a][i] - s_mean[b][i];
                    d += t * t;
                }
                local = __expf(-d);
            }
        }
        #pragma unroll
        for (int off = 16; off; off >>= 1)
            local += __shfl_xor_sync(0xffffffffu, local, off);
        if (lane == 0) s_pushw[m] = local;   // warp 29 (no pairs) writes 0
    }
    __syncthreads();

    // ---------------- Finalize per-image: warp 0, one shfl chain -----------------
    if (tid < 32) {
        int v = 0; float pl = 0.f, sc = 0.f, ps = 0.f;
        if (tid < M_PPL) {
            v  = s_valid[tid];
            ps = s_pushw[tid];
            if (v) { pl = s_pull[tid]; sc = s_dscale[tid]; }
        }
        float vf = (float)v;
        #pragma unroll
        for (int off = 16; off; off >>= 1) {
            vf += __shfl_xor_sync(0xffffffffu, vf, off);
            pl += __shfl_xor_sync(0xffffffffu, pl, off);
            sc += __shfl_xor_sync(0xffffffffu, sc, off);
            ps += __shfl_xor_sync(0xffffffffu, ps, off);
        }
        if (tid == 0) {
            const float nv = vf;
            const float safe_n = fmaxf(nv, 1.f);
            g_partial[n][0] = pl / safe_n;
            g_partial[n][1] = (nv >= 2.f) ? 0.5f * ps / fmaxf(nv * (nv - 1.f), 1.f) : 0.f;
            g_partial[n][2] = sc / safe_n;
            __threadfence();
            s_ticket = atomicAdd(&g_counter, 1u);
        }
    }
    __syncthreads();

    // ---------------- Last block: global reduce + counter reset ------------------
    if (s_ticket == N_IMG - 1) {
        if (tid < 3) {
            float acc = 0.f;
            #pragma unroll
            for (int i = 0; i < N_IMG; i++) acc += g_partial[i][tid];
            out[tid] = acc / (float)N_IMG;   // order: pull, push, scale
        }
        __threadfence();
        if (tid == 0) g_counter = 0;         // deterministic reset for next replay
    }
}

extern "C" void kernel_launch(void* const* d_in, const int* in_sizes, int n_in,
                              void* d_out, int out_size)
{
    const float* tags       = (const float*)d_in[0];
    const int*   joints     = (const int*)d_in[1];
    const float* box_scales = (const float*)d_in[2];
    const float* scale_dist = (const float*)d_in[3];
    float* out = (float*)d_out;

    ae_fused<<<N_IMG, 960>>>(tags, joints, box_scales, scale_dist, out);
}

// round 7
// speedup vs baseline: 1.0031x; 1.0031x over previous
#include <cuda_runtime.h>

#define N_IMG 16
#define M_PPL 30
#define K_JNT 17
#define S_RES 16
#define LS    1114112   // K*H*W = 17*256*256 floats per image

__device__ float g_partial[N_IMG][3];
__device__ unsigned int g_counter = 0;

__global__ __launch_bounds__(960)
void ae_fused(const float* __restrict__ tags,
              const int* __restrict__ joints,      // int32 (JAX x64 disabled)
              const float* __restrict__ box_scales,
              const float* __restrict__ scale_dist,
              float* __restrict__ out)
{
    const int n    = blockIdx.x;
    const int tid  = threadIdx.x;
    const int m    = tid >> 5;        // person (warp id), 0..29
    const int lane = tid & 31;
    const int h    = lane >> 4;       // K-half: 0 or 1
    const int s    = lane & 15;       // scale index

    __shared__ float s_mean[M_PPL][S_RES + 1];   // stride 17: conflict-free push reads
    __shared__ float s_pull[M_PPL];
    __shared__ float s_dscale[M_PPL];
    __shared__ float s_pushw[M_PPL];
    __shared__ int   s_valid[M_PPL];

    // ---------------- Phase 1: one warp per person -------------------------------
    {
        const int2* jp2 = (const int2*)(joints + (n * M_PPL + m) * K_JNT * 2);
        const float* tbase = tags + (size_t)n * LS;

        // lane handles k = h, h+2, ..., <17 (h=0: 9 joints, h=1: 8)
        int2  lv[9];
        float gv[9];
        #pragma unroll
        for (int i = 0; i < 9; i++) {
            const int k = h + 2 * i;
            if (k < K_JNT) lv[i] = __ldg(&jp2[k]);          // (loc, vis) in one 64-bit load
        }
        #pragma unroll
        for (int i = 0; i < 9; i++) {
            const int k = h + 2 * i;
            if (k < K_JNT) gv[i] = __ldg(&tbase[lv[i].x * S_RES + s]);  // coalesced 64B/group
        }

        float sumv = 0.f; int cnt = 0;
        #pragma unroll
        for (int i = 0; i < 9; i++) {
            const int k = h + 2 * i;
            if (k < K_JNT && lv[i].y > 0) { sumv += gv[i]; cnt++; }
        }
        // combine the two K-halves (lane (1-h, s))
        sumv += __shfl_xor_sync(0xffffffffu, sumv, 16);
        cnt  += __shfl_xor_sync(0xffffffffu, cnt, 16);

        const float safe_cnt = fmaxf((float)cnt, 1.f);
        const float mean = sumv / safe_cnt;
        if (h == 0) s_mean[m][s] = mean;

        float p = 0.f;
        #pragma unroll
        for (int i = 0; i < 9; i++) {
            const int k = h + 2 * i;
            if (k < K_JNT && lv[i].y > 0) { const float d = gv[i] - mean; p += d * d; }
        }

        // scale term (each s appears twice across halves -> full-warp sums = 2x, halved below)
        const float bs  = __ldg(&box_scales[n * M_PPL + m]);
        const float gap = fabsf(bs - __ldg(&scale_dist[s]));
        const float inv = 1.f / (gap + 1e-10f);
        const float am  = fabsf(mean);

        float n1 = inv * inv;
        float n2 = am * am;
        float dr = inv * am;

        #pragma unroll
        for (int off = 16; off; off >>= 1) {
            p  += __shfl_xor_sync(0xffffffffu, p,  off);
            n1 += __shfl_xor_sync(0xffffffffu, n1, off);
            n2 += __shfl_xor_sync(0xffffffffu, n2, off);
            dr += __shfl_xor_sync(0xffffffffu, dr, off);
        }

        if (lane == 0) {
            const float n1s = 0.5f * n1, n2s = 0.5f * n2, drs = 0.5f * dr;
            const float dot = drs / (fmaxf(sqrtf(n1s), 1e-12f) * fmaxf(sqrtf(n2s), 1e-12f));
            s_pull[m]   = p / (safe_cnt * (float)S_RES);
            s_dscale[m] = 1.f - dot;
            s_valid[m]  = (cnt > 0);
        }
    }
    __syncthreads();                          // barrier 1: means/valid ready

    // ---------------- Phase 2: push — 1 pair per thread, no atomics --------------
    {
        float local = 0.f;
        if (tid < M_PPL * M_PPL) {
            const int a = tid / M_PPL;
            const int b = tid - a * M_PPL;
            if (a != b && s_valid[a] && s_valid[b]) {
                float d = 0.f;
                #pragma unroll
                for (int i = 0; i < S_RES; i++) {
                    const float t = s_mean[a][i] - s_mean[b][i];
                    d += t * t;
                }
                local = __expf(-d);
            }
        }
        #pragma unroll
        for (int off = 16; off; off >>= 1)
            local += __shfl_xor_sync(0xffffffffu, local, off);
        if (lane == 0) s_pushw[m] = local;    // warp 29 (no pairs) writes 0
    }
    __syncthreads();                          // barrier 2: per-warp partials ready

    // ---------------- Tail: warp 0 only; warps 1..29 exit here -------------------
    if (tid < 32) {
        int v = 0; float pl = 0.f, sc = 0.f, ps = 0.f;
        if (tid < M_PPL) {
            v  = s_valid[tid];
            ps = s_pushw[tid];
            if (v) { pl = s_pull[tid]; sc = s_dscale[tid]; }
        }
        float vf = (float)v;
        #pragma unroll
        for (int off = 16; off; off >>= 1) {
            vf += __shfl_xor_sync(0xffffffffu, vf, off);
            pl += __shfl_xor_sync(0xffffffffu, pl, off);
            sc += __shfl_xor_sync(0xffffffffu, sc, off);
            ps += __shfl_xor_sync(0xffffffffu, ps, off);
        }

        unsigned ticket = 0u;
        if (lane == 0) {
            const float nv = vf;
            const float safe_n = fmaxf(nv, 1.f);
            g_partial[n][0] = pl / safe_n;
            g_partial[n][1] = (nv >= 2.f) ? 0.5f * ps / fmaxf(nv * (nv - 1.f), 1.f) : 0.f;
            g_partial[n][2] = sc / safe_n;
            __threadfence();
            ticket = atomicAdd(&g_counter, 1u);
        }
        ticket = __shfl_sync(0xffffffffu, ticket, 0);

        // last-arriving block: final reduce of 16x3 partials + deterministic reset
        if (ticket == N_IMG - 1) {
            if (lane < 3) {
                float s0 = 0.f;
                #pragma unroll
                for (int i = 0; i < N_IMG; i++) s0 += g_partial[i][lane];
                out[lane] = s0 / (float)N_IMG;   // order: pull, push, scale
            }
            __threadfence();
            if (lane == 0) g_counter = 0;        // reset for next graph replay
        }
    }
}

extern "C" void kernel_launch(void* const* d_in, const int* in_sizes, int n_in,
                              void* d_out, int out_size)
{
    const float* tags       = (const float*)d_in[0];
    const int*   joints     = (const int*)d_in[1];
    const float* box_scales = (const float*)d_in[2];
    const float* scale_dist = (const float*)d_in[3];
    float* out = (float*)d_out;

    ae_fused<<<N_IMG, 960>>>(tags, joints, box_scales, scale_dist, out);
}

// round 8
// speedup vs baseline: 1.0094x; 1.0063x over previous
#include <cuda_runtime.h>

#define N_IMG 16
#define M_PPL 30
#define K_JNT 17
#define S_RES 16
#define LS    1114112   // K*H*W = 17*256*256 floats per image

__device__ float g_partial[N_IMG][3];
__device__ unsigned int g_counter = 0;

__global__ __launch_bounds__(960)
void ae_fused(const float* __restrict__ tags,
              const int* __restrict__ joints,      // int32 (JAX x64 disabled)
              const float* __restrict__ box_scales,
              const float* __restrict__ scale_dist,
              float* __restrict__ out)
{
    const int n    = blockIdx.x;
    const int tid  = threadIdx.x;
    const int m    = tid >> 5;        // person (warp id), 0..29
    const int lane = tid & 31;
    const int h    = lane >> 4;       // K-half: 0 or 1
    const int s    = lane & 15;       // scale index

    __shared__ float s_mean[M_PPL][S_RES + 1];   // stride 17: conflict-free push reads
    __shared__ float s_pull[M_PPL];
    __shared__ float s_dscale[M_PPL];
    __shared__ float s_pushw[M_PPL];
    __shared__ int   s_valid[M_PPL];

    // ---------------- Phase 1: one warp per person -------------------------------
    {
        const int2* jp2 = (const int2*)(joints + (n * M_PPL + m) * K_JNT * 2);
        const float* tbase = tags + (size_t)n * LS;

        // lane handles k = h, h+2, ..., <17 (h=0: 9 joints, h=1: 8)
        int2  lv[9];
        float gv[9];
        bool  vb[9];
        #pragma unroll
        for (int i = 0; i < 9; i++) {
            const int k = h + 2 * i;
            if (k < K_JNT) lv[i] = __ldg(&jp2[k]);          // (loc, vis) in one 64-bit load
        }
        #pragma unroll
        for (int i = 0; i < 9; i++) {
            const int k = h + 2 * i;
            vb[i] = (k < K_JNT) && (lv[i].y > 0);
            if (k < K_JNT) gv[i] = __ldg(&tbase[lv[i].x * S_RES + s]);  // coalesced 64B/group
        }

        float sumv = 0.f; int cnt = 0;
        #pragma unroll
        for (int i = 0; i < 9; i++)
            if (vb[i]) { sumv += gv[i]; cnt++; }

        // combine the two K-halves (lane (1-h, s))
        sumv += __shfl_xor_sync(0xffffffffu, sumv, 16);
        cnt  += __shfl_xor_sync(0xffffffffu, cnt, 16);

        const float safe_cnt = fmaxf((float)cnt, 1.f);
        const float mean = sumv / safe_cnt;
        if (h == 0) s_mean[m][s] = mean;

        float p = 0.f;
        #pragma unroll
        for (int i = 0; i < 9; i++)
            if (vb[i]) { const float d = gv[i] - mean; p += d * d; }
        // p differs across halves -> fold halves first
        p += __shfl_xor_sync(0xffffffffu, p, 16);

        // scale term: inv/am identical in lanes s and s+16, so a 4-step butterfly
        // within each 16-lane half yields the exact full sum (no x2, no 0.5 fixup)
        const float bs  = __ldg(&box_scales[n * M_PPL + m]);
        const float gap = fabsf(bs - __ldg(&scale_dist[s]));
        const float inv = 1.f / (gap + 1e-10f);
        const float am  = fabsf(mean);

        float n1 = inv * inv;
        float n2 = am * am;
        float dr = inv * am;

        #pragma unroll
        for (int off = 8; off; off >>= 1) {
            p  += __shfl_xor_sync(0xffffffffu, p,  off);
            n1 += __shfl_xor_sync(0xffffffffu, n1, off);
            n2 += __shfl_xor_sync(0xffffffffu, n2, off);
            dr += __shfl_xor_sync(0xffffffffu, dr, off);
        }

        if (lane == 0) {
            const float dot = dr / (fmaxf(sqrtf(n1), 1e-12f) * fmaxf(sqrtf(n2), 1e-12f));
            s_pull[m]   = p / (safe_cnt * (float)S_RES);
            s_dscale[m] = 1.f - dot;
            s_valid[m]  = (cnt > 0);
        }
    }
    __syncthreads();                          // barrier 1: means/valid ready

    // ---------------- Phase 2: push — 1 pair per thread, no atomics --------------
    {
        float local = 0.f;
        if (tid < M_PPL * M_PPL) {
            const int a = tid / M_PPL;
            const int b = tid - a * M_PPL;
            if (a != b && s_valid[a] && s_valid[b]) {
                float d = 0.f;
                #pragma unroll
                for (int i = 0; i < S_RES; i++) {
                    const float t = s_mean[a][i] - s_mean[b][i];
                    d += t * t;
                }
                local = __expf(-d);
            }
        }
        #pragma unroll
        for (int off = 16; off; off >>= 1)
            local += __shfl_xor_sync(0xffffffffu, local, off);
        if (lane == 0) s_pushw[m] = local;    // warp 29 (no pairs) writes 0
    }
    __syncthreads();                          // barrier 2: per-warp partials ready

    // ---------------- Tail: warp 0 only; warps 1..29 exit here -------------------
    if (tid < 32) {
        int v = 0; float pl = 0.f, sc = 0.f, ps = 0.f;
        if (tid < M_PPL) {
            v  = s_valid[tid];
            ps = s_pushw[tid];
            if (v) { pl = s_pull[tid]; sc = s_dscale[tid]; }
        }
        float vf = (float)v;
        #pragma unroll
        for (int off = 16; off; off >>= 1) {
            vf += __shfl_xor_sync(0xffffffffu, vf, off);
            pl += __shfl_xor_sync(0xffffffffu, pl, off);
            sc += __shfl_xor_sync(0xffffffffu, sc, off);
            ps += __shfl_xor_sync(0xffffffffu, ps, off);
        }

        unsigned ticket = 0u;
        if (lane == 0) {
            const float nv = vf;
            const float safe_n = fmaxf(nv, 1.f);
            g_partial[n][0] = pl / safe_n;
            g_partial[n][1] = (nv >= 2.f) ? 0.5f * ps / fmaxf(nv * (nv - 1.f), 1.f) : 0.f;
            g_partial[n][2] = sc / safe_n;
            __threadfence();
            ticket = atomicAdd(&g_counter, 1u);
        }
        ticket = __shfl_sync(0xffffffffu, ticket, 0);

        // last-arriving block: final reduce of 16x3 partials + deterministic reset
        if (ticket == N_IMG - 1) {
            if (lane < 3) {
                float s0 = 0.f;
                #pragma unroll
                for (int i = 0; i < N_IMG; i++) s0 += g_partial[i][lane];
                out[lane] = s0 / (float)N_IMG;   // order: pull, push, scale
            }
            __threadfence();
            if (lane == 0) g_counter = 0;        // reset for next graph replay
        }
    }
}

extern "C" void kernel_launch(void* const* d_in, const int* in_sizes, int n_in,
                              void* d_out, int out_size)
{
    const float* tags       = (const float*)d_in[0];
    const int*   joints     = (const int*)d_in[1];
    const float* box_scales = (const float*)d_in[2];
    const float* scale_dist = (const float*)d_in[3];
    float* out = (float*)d_out;

    ae_fused<<<N_IMG, 960>>>(tags, joints, box_scales, scale_dist, out);
}

// round 9
// speedup vs baseline: 1.1383x; 1.1277x over previous
#include <cuda_runtime.h>

#define N_IMG 16
#define M_PPL 30
#define K_JNT 17
#define S_RES 16
#define LS    1114112   // K*H*W = 17*256*256 floats per image

__device__ float g_acc[3] = {0.f, 0.f, 0.f};   // running sums; reset by last block each call
__device__ unsigned int g_counter = 0;

__global__ __launch_bounds__(960)
void ae_fused(const float* __restrict__ tags,
              const int* __restrict__ joints,      // int32 (JAX x64 disabled)
              const float* __restrict__ box_scales,
              const float* __restrict__ scale_dist,
              float* __restrict__ out)
{
    const int n    = blockIdx.x;
    const int tid  = threadIdx.x;
    const int m    = tid >> 5;        // person (warp id), 0..29
    const int lane = tid & 31;
    const int h    = lane >> 4;       // K-half: 0 or 1
    const int s    = lane & 15;       // scale index

    __shared__ float s_mean[M_PPL][S_RES + 1];   // stride 17: conflict-free push reads
    __shared__ float s_pull[M_PPL];
    __shared__ float s_dscale[M_PPL];
    __shared__ float s_pushw[M_PPL];
    __shared__ int   s_valid[M_PPL];

    // ---------------- Phase 1: one warp per person -------------------------------
    {
        const int2* jp2 = (const int2*)(joints + (n * M_PPL + m) * K_JNT * 2);
        const float* tbase = tags + (size_t)n * LS;

        // lane handles k = h, h+2, ..., <17 (h=0: 9 joints, h=1: 8)
        int2  lv[9];
        float gv[9];
        bool  vb[9];
        #pragma unroll
        for (int i = 0; i < 9; i++) {
            const int k = h + 2 * i;
            if (k < K_JNT) lv[i] = __ldg(&jp2[k]);          // (loc, vis) in one 64-bit load
        }
        #pragma unroll
        for (int i = 0; i < 9; i++) {
            const int k = h + 2 * i;
            vb[i] = (k < K_JNT) && (lv[i].y > 0);
            if (k < K_JNT) gv[i] = __ldg(&tbase[lv[i].x * S_RES + s]);  // coalesced 64B/group
        }

        float sumv = 0.f; int cnt = 0;
        #pragma unroll
        for (int i = 0; i < 9; i++)
            if (vb[i]) { sumv += gv[i]; cnt++; }

        // combine the two K-halves (lane (1-h, s))
        sumv += __shfl_xor_sync(0xffffffffu, sumv, 16);
        cnt  += __shfl_xor_sync(0xffffffffu, cnt, 16);

        const float safe_cnt = fmaxf((float)cnt, 1.f);
        const float mean = sumv / safe_cnt;
        if (h == 0) s_mean[m][s] = mean;

        float p = 0.f;
        #pragma unroll
        for (int i = 0; i < 9; i++)
            if (vb[i]) { const float d = gv[i] - mean; p += d * d; }
        // p differs across halves -> fold halves first
        p += __shfl_xor_sync(0xffffffffu, p, 16);

        // scale term: inv/am identical in lanes s and s+16, so a 4-step butterfly
        // within each 16-lane half yields the exact full sum
        const float bs  = __ldg(&box_scales[n * M_PPL + m]);
        const float gap = fabsf(bs - __ldg(&scale_dist[s]));
        const float inv = 1.f / (gap + 1e-10f);
        const float am  = fabsf(mean);

        float n1 = inv * inv;
        float n2 = am * am;
        float dr = inv * am;

        #pragma unroll
        for (int off = 8; off; off >>= 1) {
            p  += __shfl_xor_sync(0xffffffffu, p,  off);
            n1 += __shfl_xor_sync(0xffffffffu, n1, off);
            n2 += __shfl_xor_sync(0xffffffffu, n2, off);
            dr += __shfl_xor_sync(0xffffffffu, dr, off);
        }

        if (lane == 0) {
            const float dot = dr / (fmaxf(sqrtf(n1), 1e-12f) * fmaxf(sqrtf(n2), 1e-12f));
            s_pull[m]   = p / (safe_cnt * (float)S_RES);
            s_dscale[m] = 1.f - dot;
            s_valid[m]  = (cnt > 0);
        }
    }
    __syncthreads();                          // barrier 1: means/valid ready

    // ---------------- Phase 2: push — 1 pair per thread, no atomics --------------
    {
        float local = 0.f;
        if (tid < M_PPL * M_PPL) {
            const int a = tid / M_PPL;
            const int b = tid - a * M_PPL;
            if (a != b && s_valid[a] && s_valid[b]) {
                float d = 0.f;
                #pragma unroll
                for (int i = 0; i < S_RES; i++) {
                    const float t = s_mean[a][i] - s_mean[b][i];
                    d += t * t;
                }
                local = __expf(-d);
            }
        }
        #pragma unroll
        for (int off = 16; off; off >>= 1)
            local += __shfl_xor_sync(0xffffffffu, local, off);
        if (lane == 0) s_pushw[m] = local;    // warp 29 (no pairs) writes 0
    }
    __syncthreads();                          // barrier 2: per-warp partials ready

    // ---------------- Tail: warp 0 only; warps 1..29 exit here -------------------
    if (tid < 32) {
        int v = 0; float pl = 0.f, sc = 0.f, ps = 0.f;
        if (tid < M_PPL) {
            v  = s_valid[tid];
            ps = s_pushw[tid];
            if (v) { pl = s_pull[tid]; sc = s_dscale[tid]; }
        }
        float vf = (float)v;
        #pragma unroll
        for (int off = 16; off; off >>= 1) {
            vf += __shfl_xor_sync(0xffffffffu, vf, off);
            pl += __shfl_xor_sync(0xffffffffu, pl, off);
            sc += __shfl_xor_sync(0xffffffffu, sc, off);
            ps += __shfl_xor_sync(0xffffffffu, ps, off);
        }

        unsigned ticket = 0u;
        if (lane == 0) {
            const float nv = vf;
            const float inv_n = 1.f / (fmaxf(nv, 1.f) * (float)N_IMG);  // fold 1/N_IMG here
            const float push_c = (nv >= 2.f)
                ? 0.5f * ps / (fmaxf(nv * (nv - 1.f), 1.f) * (float)N_IMG)
                : 0.f;
            atomicAdd(&g_acc[0], pl * inv_n);     // pull contribution
            atomicAdd(&g_acc[1], push_c);         // push contribution
            atomicAdd(&g_acc[2], sc * inv_n);     // scale contribution
            __threadfence();                      // order accumulates before ticket
            ticket = atomicAdd(&g_counter, 1u);
        }
        ticket = __shfl_sync(0xffffffffu, ticket, 0);

        // last-arriving block: emit result + deterministic reset for next replay
        if (ticket == N_IMG - 1 && lane < 3) {
            out[lane] = g_acc[lane];              // order: pull, push, scale
            g_acc[lane] = 0.f;
            if (lane == 0) g_counter = 0;
        }
    }
}

extern "C" void kernel_launch(void* const* d_in, const int* in_sizes, int n_in,
                              void* d_out, int out_size)
{
    const float* tags       = (const float*)d_in[0];
    const int*   joints     = (const int*)d_in[1];
    const float* box_scales = (const float*)d_in[2];
    const float* scale_dist = (const float*)d_in[3];
    float* out = (float*)d_out;

    ae_fused<<<N_IMG, 960>>>(tags, joints, box_scales, scale_dist, out);
}

// round 10
// speedup vs baseline: 1.2490x; 1.0973x over previous
#include <cuda_runtime.h>

#define N_IMG 16
#define M_PPL 30
#define K_JNT 17
#define S_RES 16
#define LS    1114112   // K*H*W = 17*256*256 floats per image

__global__ void zero_out(float* __restrict__ out)
{
    if (threadIdx.x < 3) out[threadIdx.x] = 0.f;
}

__global__ __launch_bounds__(960)
void ae_fused(const float* __restrict__ tags,
              const int* __restrict__ joints,      // int32 (JAX x64 disabled)
              const float* __restrict__ box_scales,
              const float* __restrict__ scale_dist,
              float* __restrict__ out)
{
    const int n    = blockIdx.x;
    const int tid  = threadIdx.x;
    const int m    = tid >> 5;        // person (warp id), 0..29
    const int lane = tid & 31;
    const int h    = lane >> 4;       // K-half: 0 or 1
    const int s    = lane & 15;       // scale index

    __shared__ float s_mean[M_PPL][S_RES + 1];   // stride 17: conflict-free push reads
    __shared__ float s_pull[M_PPL];
    __shared__ float s_dscale[M_PPL];
    __shared__ float s_pushw[M_PPL];
    __shared__ int   s_valid[M_PPL];

    // ---------------- Phase 1: one warp per person -------------------------------
    {
        const int2* jp2 = (const int2*)(joints + (n * M_PPL + m) * K_JNT * 2);
        const float* tbase = tags + (size_t)n * LS;

        // lane handles k = h, h+2, ..., <17 (h=0: 9 joints, h=1: 8)
        int2  lv[9];
        float gv[9];
        bool  vb[9];
        #pragma unroll
        for (int i = 0; i < 9; i++) {
            const int k = h + 2 * i;
            if (k < K_JNT) lv[i] = __ldg(&jp2[k]);          // (loc, vis) in one 64-bit load
        }
        #pragma unroll
        for (int i = 0; i < 9; i++) {
            const int k = h + 2 * i;
            vb[i] = (k < K_JNT) && (lv[i].y > 0);
            if (k < K_JNT) gv[i] = __ldg(&tbase[lv[i].x * S_RES + s]);  // coalesced 64B/group
        }

        float sumv = 0.f; int cnt = 0;
        #pragma unroll
        for (int i = 0; i < 9; i++)
            if (vb[i]) { sumv += gv[i]; cnt++; }

        // combine the two K-halves (lane (1-h, s))
        sumv += __shfl_xor_sync(0xffffffffu, sumv, 16);
        cnt  += __shfl_xor_sync(0xffffffffu, cnt, 16);

        const float safe_cnt = fmaxf((float)cnt, 1.f);
        const float mean = sumv / safe_cnt;
        if (h == 0) s_mean[m][s] = mean;

        float p = 0.f;
        #pragma unroll
        for (int i = 0; i < 9; i++)
            if (vb[i]) { const float d = gv[i] - mean; p += d * d; }
        // p differs across halves -> fold halves first
        p += __shfl_xor_sync(0xffffffffu, p, 16);

        // scale term: inv/am identical in lanes s and s+16, so a 4-step butterfly
        // within each 16-lane half yields the exact full sum
        const float bs  = __ldg(&box_scales[n * M_PPL + m]);
        const float gap = fabsf(bs - __ldg(&scale_dist[s]));
        const float inv = 1.f / (gap + 1e-10f);
        const float am  = fabsf(mean);

        float n1 = inv * inv;
        float n2 = am * am;
        float dr = inv * am;

        #pragma unroll
        for (int off = 8; off; off >>= 1) {
            p  += __shfl_xor_sync(0xffffffffu, p,  off);
            n1 += __shfl_xor_sync(0xffffffffu, n1, off);
            n2 += __shfl_xor_sync(0xffffffffu, n2, off);
            dr += __shfl_xor_sync(0xffffffffu, dr, off);
        }

        if (lane == 0) {
            const float dot = dr / (fmaxf(sqrtf(n1), 1e-12f) * fmaxf(sqrtf(n2), 1e-12f));
            s_pull[m]   = p / (safe_cnt * (float)S_RES);
            s_dscale[m] = 1.f - dot;
            s_valid[m]  = (cnt > 0);
        }
    }
    __syncthreads();                          // barrier 1: means/valid ready

    // ---------------- Phase 2: push — 1 pair per thread, no atomics --------------
    {
        float local = 0.f;
        if (tid < M_PPL * M_PPL) {
            const int a = tid / M_PPL;
            const int b = tid - a * M_PPL;
            if (a != b && s_valid[a] && s_valid[b]) {
                float d = 0.f;
                #pragma unroll
                for (int i = 0; i < S_RES; i++) {
                    const float t = s_mean[a][i] - s_mean[b][i];
                    d += t * t;
                }
                local = __expf(-d);
            }
        }
        #pragma unroll
        for (int off = 16; off; off >>= 1)
            local += __shfl_xor_sync(0xffffffffu, local, off);
        if (lane == 0) s_pushw[m] = local;    // warp 29 (no pairs) writes 0
    }
    __syncthreads();                          // barrier 2: per-warp partials ready

    // ---------------- Tail: warp 0 only; fire-and-forget REDs into out -----------
    if (tid < 32) {
        int v = 0; float pl = 0.f, sc = 0.f, ps = 0.f;
        if (tid < M_PPL) {
            v  = s_valid[tid];
            ps = s_pushw[tid];
            if (v) { pl = s_pull[tid]; sc = s_dscale[tid]; }
        }
        float vf = (float)v;
        #pragma unroll
        for (int off = 16; off; off >>= 1) {
            vf += __shfl_xor_sync(0xffffffffu, vf, off);
            pl += __shfl_xor_sync(0xffffffffu, pl, off);
            sc += __shfl_xor_sync(0xffffffffu, sc, off);
            ps += __shfl_xor_sync(0xffffffffu, ps, off);
        }

        if (lane == 0) {
            const float nv = vf;
            const float inv_n = 1.f / (fmaxf(nv, 1.f) * (float)N_IMG);  // fold 1/N_IMG
            const float push_c = (nv >= 2.f)
                ? 0.5f * ps / (fmaxf(nv * (nv - 1.f), 1.f) * (float)N_IMG)
                : 0.f;
            atomicAdd(&out[0], pl * inv_n);   // pull   (RED, no return -> no wait)
            atomicAdd(&out[1], push_c);       // push
            atomicAdd(&out[2], sc * inv_n);   // scale
        }
    }
}

extern "C" void kernel_launch(void* const* d_in, const int* in_sizes, int n_in,
                              void* d_out, int out_size)
{
    const float* tags       = (const float*)d_in[0];
    const int*   joints     = (const int*)d_in[1];
    const float* box_scales = (const float*)d_in[2];
    const float* scale_dist = (const float*)d_in[3];
    float* out = (float*)d_out;

    zero_out<<<1, 32>>>(out);
    ae_fused<<<N_IMG, 960>>>(tags, joints, box_scales, scale_dist, out);
}